// round 1
// baseline (speedup 1.0000x reference)
#include <cuda_runtime.h>

// Local contrast normalization, fused single kernel.
// x: [B,512,512,1] fp32 -> out same shape.
// w = outer(u,u)/sum, u[i] = exp(-(i-4.5)^2/3), i=0..8 (asymmetric!).
// mean = conv(x,w); d = x - mean; n = sqrt(conv(d*d, w));
// out = (n > 0.5) ? d/n : d.   Both convs SAME zero-pad.

static constexpr int HH = 512;
static constexpr int WW = 512;
static constexpr int TY = 32;          // output tile rows
static constexpr int TX = 64;          // output tile cols
static constexpr int XR = TY + 16;     // 48 x-tile rows
static constexpr int XC = TX + 16;     // 80 x-tile cols
static constexpr int TMPC = TX + 8;    // 72 h-conv cols
static constexpr int DR = TY + 8;      // 40 d rows
static constexpr int DC = TX + 8;      // 72 d cols

__global__ __launch_bounds__(256)
void lcn_kernel(const float* __restrict__ x, float* __restrict__ out) {
    __shared__ float sx[XR * XC];      // 48*80  = 3840 floats   (x tile)
    __shared__ float st[XR * TMPC];    // 48*72  = 3456 floats   (h-conv of x; reused as tmp2[40*64])
    __shared__ float sd[DR * DC];      // 40*72  = 2880 floats   (demeaned)

    const int tid = threadIdx.x;
    const int ox = blockIdx.x * TX;
    const int oy = blockIdx.y * TY;
    const long base = (long)blockIdx.z * HH * WW;

    // 1-D normalized Gaussian taps (asymmetric: center at 4.5)
    float v[9];
    {
        float s = 0.f;
        #pragma unroll
        for (int i = 0; i < 9; i++) {
            float t = (float)i - 4.5f;
            v[i] = expf(-t * t * (1.0f / 3.0f));
            s += v[i];
        }
        float inv = 1.0f / s;
        #pragma unroll
        for (int i = 0; i < 9; i++) v[i] *= inv;
    }

    // ---------- stage 0: load x tile (zero-padded at image borders) ----------
    {
        const int gy0 = oy - 8, gx0 = ox - 8;
        for (int idx = tid; idx < XR * XC; idx += 256) {
            int r = idx / XC, c = idx - r * XC;
            int gy = gy0 + r, gx = gx0 + c;
            float val = 0.f;
            if ((unsigned)gy < (unsigned)HH && (unsigned)gx < (unsigned)WW)
                val = __ldg(x + base + (long)gy * WW + gx);
            sx[idx] = val;
        }
    }
    __syncthreads();

    // ---------- stage 1: horizontal conv of x -> st[48][72] ----------
    // st[r][c] = sum_j v[j] * sx[r][c+j]
    {
        for (int wi = tid; wi < XR * 9; wi += 256) {   // 9 chunks of 8 cols per row
            int r = wi / 9, c0 = (wi - r * 9) * 8;
            float a[16];
            const float4* p = (const float4*)(sx + r * XC + c0);
            #pragma unroll
            for (int q = 0; q < 4; q++) {
                float4 f = p[q];
                a[4*q] = f.x; a[4*q+1] = f.y; a[4*q+2] = f.z; a[4*q+3] = f.w;
            }
            float o[8];
            #pragma unroll
            for (int k = 0; k < 8; k++) {
                float acc = v[0] * a[k];
                #pragma unroll
                for (int j = 1; j < 9; j++) acc = fmaf(v[j], a[k + j], acc);
                o[k] = acc;
            }
            float4* po = (float4*)(st + r * TMPC + c0);
            po[0] = make_float4(o[0], o[1], o[2], o[3]);
            po[1] = make_float4(o[4], o[5], o[6], o[7]);
        }
    }
    __syncthreads();

    // ---------- stage 2: vertical conv -> mean; d = x - mean -> sd[40][72] ----------
    // d is zero OUTSIDE the image (conv SAME zero-pads the demeaned array itself).
    {
        for (int wi = tid; wi < 5 * DC; wi += 256) {   // 5 chunks of 8 rows x 72 cols
            int c = wi % DC;
            int r0 = (wi / DC) * 8;
            float a[16];
            #pragma unroll
            for (int t = 0; t < 16; t++) a[t] = st[(r0 + t) * TMPC + c];
            #pragma unroll
            for (int k = 0; k < 8; k++) {
                float acc = v[0] * a[k];
                #pragma unroll
                for (int j = 1; j < 9; j++) acc = fmaf(v[j], a[k + j], acc);
                float d = sx[(r0 + k + 4) * XC + (c + 4)] - acc;
                int gy = oy - 4 + r0 + k;
                int gx = ox - 4 + c;
                if ((unsigned)gy >= (unsigned)HH || (unsigned)gx >= (unsigned)WW) d = 0.f;
                sd[(r0 + k) * DC + c] = d;
            }
        }
    }
    __syncthreads();

    // ---------- stage 3: horizontal conv of d^2 -> st (reused as tmp2[40][64]) ----------
    {
        for (int wi = tid; wi < DR * 8; wi += 256) {   // 8 chunks of 8 cols per row
            int r = wi / 8, c0 = (wi - r * 8) * 8;
            float a[16];
            const float4* p = (const float4*)(sd + r * DC + c0);
            #pragma unroll
            for (int q = 0; q < 4; q++) {
                float4 f = p[q];
                a[4*q]   = f.x * f.x;
                a[4*q+1] = f.y * f.y;
                a[4*q+2] = f.z * f.z;
                a[4*q+3] = f.w * f.w;
            }
            float o[8];
            #pragma unroll
            for (int k = 0; k < 8; k++) {
                float acc = v[0] * a[k];
                #pragma unroll
                for (int j = 1; j < 9; j++) acc = fmaf(v[j], a[k + j], acc);
                o[k] = acc;
            }
            float4* po = (float4*)(st + r * TX + c0);
            po[0] = make_float4(o[0], o[1], o[2], o[3]);
            po[1] = make_float4(o[4], o[5], o[6], o[7]);
        }
    }
    __syncthreads();

    // ---------- stage 4: vertical conv -> var; finalize & store ----------
    {
        int c  = tid & 63;           // 0..63
        int r0 = (tid >> 6) * 8;     // 0,8,16,24
        float a[16];
        #pragma unroll
        for (int t = 0; t < 16; t++) a[t] = st[(r0 + t) * TX + c];
        #pragma unroll
        for (int k = 0; k < 8; k++) {
            float acc = v[0] * a[k];
            #pragma unroll
            for (int j = 1; j < 9; j++) acc = fmaf(v[j], a[k + j], acc);
            float nrm = sqrtf(acc);
            float d = sd[(r0 + k + 4) * DC + (c + 4)];
            float res = (nrm > 0.5f) ? (d / nrm) : d;
            out[base + (long)(oy + r0 + k) * WW + (ox + c)] = res;
        }
    }
}

extern "C" void kernel_launch(void* const* d_in, const int* in_sizes, int n_in,
                              void* d_out, int out_size) {
    const float* x = (const float*)d_in[0];
    float* out = (float*)d_out;
    int B = in_sizes[0] / (HH * WW);
    dim3 grid(WW / TX, HH / TY, B);
    lcn_kernel<<<grid, 256>>>(x, out);
}

// round 2
// speedup vs baseline: 1.6919x; 1.6919x over previous
#include <cuda_runtime.h>

// Local contrast normalization, fused, transposed-stage design.
// x: [B,512,512,1] fp32. w = outer(u,u)/sum, u[i]=exp(-(i-4.5)^2/3).
// mean = conv(x,w); d = x-mean; n = sqrt(conv(d*d,w));
// out = (n>0.5) ? d/n : d. Both convs SAME zero-pad.

static constexpr int HH = 512, WW = 512;
static constexpr int TY = 32, TX = 64;

// smem strides engineered: multiples of 4 (float4 align), stride%32 in {20,12}
// so LDS.128 8-thread phases hit disjoint bank quads.
static constexpr int SX_C = 84;   // sx: 48 rows x 80 used cols   (84%32=20)
static constexpr int ST_C = 52;   // stT: 72 "rows"(cols) x 48    (52%32=20)
static constexpr int SD_C = 76;   // sd: 40 rows x 72 used cols   (76%32=12)
static constexpr int T2_C = 44;   // st2T: 64 "rows" x 40         (44%32=12)

// 1-D normalized Gaussian taps, exp(-(i-4.5)^2/3)/S, precomputed as literals
// so ptxas emits FFMA with immediate (rt_SMSP=1 instead of 2).
#define K0 0.000381553f
#define K1 0.00549127f
#define K2 0.04057532f
#define K3 0.15392929f
#define K4 0.29981330f
__device__ constexpr float KV[9] = {K0, K1, K2, K3, K4, K4, K3, K2, K1};

__device__ __forceinline__ void conv9x8(const float a[16], float o[8]) {
    #pragma unroll
    for (int k = 0; k < 8; k++) {
        float acc = KV[0] * a[k];
        #pragma unroll
        for (int j = 1; j < 9; j++) acc = fmaf(KV[j], a[k + j], acc);
        o[k] = acc;
    }
}

__device__ __forceinline__ void ld16(const float* __restrict__ p, float a[16]) {
    #pragma unroll
    for (int q = 0; q < 4; q++) {
        float4 f = ((const float4*)p)[q];
        a[4*q] = f.x; a[4*q+1] = f.y; a[4*q+2] = f.z; a[4*q+3] = f.w;
    }
}

__global__ __launch_bounds__(256)
void lcn_kernel(const float* __restrict__ x, float* __restrict__ out) {
    __shared__ float sx[48 * SX_C];   // x tile, rows oy-8..oy+39, cols ox-8..ox+71
    __shared__ float sb[72 * ST_C];   // stT (h-conv of x, transposed); later st2T
    __shared__ float sd[40 * SD_C];   // demeaned (row-major), rows oy-4.., cols ox-4..

    const int tid = threadIdx.x;
    const int ox = blockIdx.x * TX;
    const int oy = blockIdx.y * TY;
    const long base = (long)blockIdx.z * (HH * WW);

    // ---- stage 0: load x tile as float4 (per-vector predicates) ----
    #pragma unroll 1
    for (int idx = tid; idx < 48 * 20; idx += 256) {
        int r = idx / 20, g = idx - r * 20;
        int gy = oy - 8 + r;
        int gx = ox - 8 + g * 4;               // multiple of 4 -> vector all-in or all-out
        float4 v = make_float4(0.f, 0.f, 0.f, 0.f);
        if ((unsigned)gy < (unsigned)HH && (unsigned)gx < (unsigned)WW)
            v = *(const float4*)(x + base + (long)gy * WW + gx);
        *(float4*)(sx + r * SX_C + g * 4) = v;
    }
    __syncthreads();

    // ---- stage 1: h-conv of x -> stT[c][r] (c=0..71 <-> gx=ox-4+c; r=0..47) ----
    #pragma unroll 1
    for (int idx = tid; idx < 9 * 48; idx += 256) {
        int ch = idx / 48, r = idx - ch * 48;
        int c0 = ch * 8;
        float a[16], o[8];
        ld16(sx + r * SX_C + c0, a);
        conv9x8(a, o);
        #pragma unroll
        for (int k = 0; k < 8; k++) sb[(c0 + k) * ST_C + r] = o[k];
    }
    __syncthreads();

    // ---- stage 2: v-conv (as h-conv on stT rows) -> d, masked, row-major sd ----
    #pragma unroll 1
    for (int idx = tid; idx < 5 * 72; idx += 256) {
        int rb = idx / 72, c = idx - rb * 72;
        int r0 = rb * 8;
        float a[16], o[8];
        ld16(sb + c * ST_C + r0, a);
        conv9x8(a, o);
        const bool colok = (unsigned)(ox - 4 + c) < (unsigned)WW;
        const int gy0 = oy - 4 + r0;
        #pragma unroll
        for (int k = 0; k < 8; k++) {
            float d = sx[(r0 + k + 4) * SX_C + (c + 4)] - o[k];
            bool ok = colok && ((unsigned)(gy0 + k) < (unsigned)HH);
            sd[(r0 + k) * SD_C + c] = ok ? d : 0.f;
        }
    }
    __syncthreads();

    // ---- stage 3: h-conv of d^2 -> st2T[c][r] (aliases sb; c=0..63 <-> gx=ox+c) ----
    #pragma unroll 1
    for (int idx = tid; idx < 8 * 40; idx += 256) {
        int ch = idx / 40, r = idx - ch * 40;
        int c0 = ch * 8;
        float a[16], o[8];
        ld16(sd + r * SD_C + c0, a);
        #pragma unroll
        for (int t = 0; t < 16; t++) a[t] *= a[t];
        conv9x8(a, o);
        #pragma unroll
        for (int k = 0; k < 8; k++) sb[(c0 + k) * T2_C + r] = o[k];
    }
    __syncthreads();

    // ---- stage 4: v-conv of t2 -> var; finalize; coalesced scalar STG ----
    {
        int c = tid & 63;
        int r0 = (tid >> 6) * 8;
        float a[16], o[8];
        ld16(sb + c * T2_C + r0, a);
        conv9x8(a, o);
        #pragma unroll
        for (int k = 0; k < 8; k++) {
            float nrm = sqrtf(o[k]);
            float d = sd[(r0 + 4 + k) * SD_C + (c + 4)];
            float res = (nrm > 0.5f) ? (d / nrm) : d;
            out[base + (long)(oy + r0 + k) * WW + (ox + c)] = res;
        }
    }
}

extern "C" void kernel_launch(void* const* d_in, const int* in_sizes, int n_in,
                              void* d_out, int out_size) {
    const float* x = (const float*)d_in[0];
    float* out = (float*)d_out;
    int B = in_sizes[0] / (HH * WW);
    dim3 grid(WW / TX, HH / TY, B);
    lcn_kernel<<<grid, 256>>>(x, out);
}